// round 2
// baseline (speedup 1.0000x reference)
#include <cuda_runtime.h>
#include <math.h>

// MySupConLoss fused kernel, round 0: fp32 SIMT tiled GEMM + fused epilogue.
//
// loss_i = log(sum_j e_ij*neg_ij) - (sum_j e_ij*pos_ij)/card_i   (card>0; else 0)
// e_ij = exp(dot(fn_i,fn_j)/T - m_i),  m_i = ||fn_i||^2/T (row max = diagonal)
// out = mean_i loss_i

#define NROWS 8192
#define DDIM  512
#define INV_T (1.0f / 0.07f)

#define BM 64
#define BN 64
#define BK 16
#define CTILES_PER_BLOCK 16   // 16*64 = 1024 columns per block; grid.y = 8
#define COL_SPLITS 8

// Scratch (device globals: no allocation allowed in kernel_launch)
__device__ float g_fn[(size_t)NROWS * DDIM];   // normalized features, 16 MB
__device__ float g_m[NROWS];                   // per-row logits_max (= selfdot/T)
__device__ float g_spos[NROWS];
__device__ float g_sneg[NROWS];
__device__ float g_card[NROWS];

// ---------------------------------------------------------------------------
// Kernel 1: normalize rows, compute m_i. One block per row, 128 threads.
// ---------------------------------------------------------------------------
__global__ __launch_bounds__(128) void k_normalize(const float* __restrict__ f) {
    int row = blockIdx.x;
    const float4* fr = reinterpret_cast<const float4*>(f + (size_t)row * DDIM);
    float4 v = fr[threadIdx.x];  // 128 threads * 4 = 512
    float ss = v.x * v.x + v.y * v.y + v.z * v.z + v.w * v.w;
    #pragma unroll
    for (int o = 16; o; o >>= 1) ss += __shfl_xor_sync(0xffffffffu, ss, o);
    __shared__ float s[4];
    if ((threadIdx.x & 31) == 0) s[threadIdx.x >> 5] = ss;
    __syncthreads();
    float tot = s[0] + s[1] + s[2] + s[3];
    float nrm = fmaxf(sqrtf(tot), 1e-8f);
    float inv = 1.0f / nrm;
    float4 o4 = make_float4(v.x * inv, v.y * inv, v.z * inv, v.w * inv);
    reinterpret_cast<float4*>(g_fn + (size_t)row * DDIM)[threadIdx.x] = o4;
    if (threadIdx.x == 0) g_m[row] = tot * inv * inv * INV_T;  // ~= 1/T
}

// ---------------------------------------------------------------------------
// Kernel 2: zero the per-row accumulators (required every graph replay).
// ---------------------------------------------------------------------------
__global__ void k_zero() {
    int i = blockIdx.x * blockDim.x + threadIdx.x;
    if (i < NROWS) { g_spos[i] = 0.f; g_sneg[i] = 0.f; g_card[i] = 0.f; }
}

// ---------------------------------------------------------------------------
// Kernel 3: fused GEMM + exp + mask accumulation.
// Block: 256 threads as 16x16, thread tile 4x4, tile 64x64, K-step 16.
// Each block: one 64-row stripe x 1024 columns (16 column tiles).
// ---------------------------------------------------------------------------
__global__ __launch_bounds__(256) void k_main(const int* __restrict__ pos,
                                              const int* __restrict__ neg) {
    __shared__ float As[BK][BM];
    __shared__ float Bs[BK][BN];

    const int tid = threadIdx.x;
    const int tx = tid & 15;         // column group
    const int ty = tid >> 4;         // row group
    const int rowBase = blockIdx.x * BM;
    const int colStart = blockIdx.y * (CTILES_PER_BLOCK * BN);

    // global-load mapping for the 64x16 tiles
    const int lr = tid >> 2;         // 0..63: row within tile
    const int lk = (tid & 3) * 4;    // 0,4,8,12: k offset (float4)

    float mrow[4];
    #pragma unroll
    for (int mi = 0; mi < 4; mi++) mrow[mi] = g_m[rowBase + ty * 4 + mi];

    float spos[4] = {0.f, 0.f, 0.f, 0.f};
    float sneg[4] = {0.f, 0.f, 0.f, 0.f};
    float card[4] = {0.f, 0.f, 0.f, 0.f};

    for (int ct = 0; ct < CTILES_PER_BLOCK; ct++) {
        const int colBase = colStart + ct * BN;
        float acc[4][4];
        #pragma unroll
        for (int mi = 0; mi < 4; mi++)
            #pragma unroll
            for (int ni = 0; ni < 4; ni++) acc[mi][ni] = 0.f;

        for (int k0 = 0; k0 < DDIM; k0 += BK) {
            float4 a = *reinterpret_cast<const float4*>(
                g_fn + (size_t)(rowBase + lr) * DDIM + k0 + lk);
            float4 b = *reinterpret_cast<const float4*>(
                g_fn + (size_t)(colBase + lr) * DDIM + k0 + lk);
            __syncthreads();   // protect previous tile's reads
            As[lk + 0][lr] = a.x; As[lk + 1][lr] = a.y;
            As[lk + 2][lr] = a.z; As[lk + 3][lr] = a.w;
            Bs[lk + 0][lr] = b.x; Bs[lk + 1][lr] = b.y;
            Bs[lk + 2][lr] = b.z; Bs[lk + 3][lr] = b.w;
            __syncthreads();
            #pragma unroll
            for (int kk = 0; kk < BK; kk++) {
                float4 ra = *reinterpret_cast<const float4*>(&As[kk][ty * 4]);
                float4 rb = *reinterpret_cast<const float4*>(&Bs[kk][tx * 4]);
                float av[4] = {ra.x, ra.y, ra.z, ra.w};
                float bv[4] = {rb.x, rb.y, rb.z, rb.w};
                #pragma unroll
                for (int mi = 0; mi < 4; mi++)
                    #pragma unroll
                    for (int ni = 0; ni < 4; ni++)
                        acc[mi][ni] = fmaf(av[mi], bv[ni], acc[mi][ni]);
            }
        }

        // Epilogue: exp + mask accumulation for this 64x64 tile
        #pragma unroll
        for (int mi = 0; mi < 4; mi++) {
            const int i  = rowBase + ty * 4 + mi;
            const int jb = colBase + tx * 4;
            const int4 p4 = *reinterpret_cast<const int4*>(pos + (size_t)i * NROWS + jb);
            const int4 n4 = *reinterpret_cast<const int4*>(neg + (size_t)i * NROWS + jb);
            const int pv[4] = {p4.x, p4.y, p4.z, p4.w};
            const int nv[4] = {n4.x, n4.y, n4.z, n4.w};
            #pragma unroll
            for (int ni = 0; ni < 4; ni++) {
                const int j = jb + ni;
                float e = __expf(fmaf(acc[mi][ni], INV_T, -mrow[mi]));
                float valid = (j != i) ? 1.0f : 0.0f;
                float pf = (float)pv[ni] * valid;
                float nf = (float)nv[ni] * valid;
                spos[mi] = fmaf(pf, e, spos[mi]);
                sneg[mi] = fmaf(nf, e, sneg[mi]);
                card[mi] += pf;
            }
        }
    }

    // Reduce across tx (lanes 0..15 / 16..31 within each warp share rows)
    #pragma unroll
    for (int mi = 0; mi < 4; mi++) {
        float a = spos[mi], b = sneg[mi], c = card[mi];
        #pragma unroll
        for (int o = 8; o; o >>= 1) {
            a += __shfl_xor_sync(0xffffffffu, a, o);
            b += __shfl_xor_sync(0xffffffffu, b, o);
            c += __shfl_xor_sync(0xffffffffu, c, o);
        }
        if (tx == 0) {
            const int i = rowBase + ty * 4 + mi;
            atomicAdd(&g_spos[i], a);
            atomicAdd(&g_sneg[i], b);
            atomicAdd(&g_card[i], c);
        }
    }
}

// ---------------------------------------------------------------------------
// Kernel 4: finalize. loss_i = log(sneg_i) - spos_i/card_i (card>0), mean.
// ---------------------------------------------------------------------------
__global__ __launch_bounds__(256) void k_finalize(float* __restrict__ out) {
    __shared__ float s[256];
    float sum = 0.f;
    for (int i = threadIdx.x; i < NROWS; i += 256) {
        float c = g_card[i];
        float l = 0.f;
        if (c > 0.f) l = logf(g_sneg[i]) - g_spos[i] / c;
        sum += l;
    }
    s[threadIdx.x] = sum;
    __syncthreads();
    #pragma unroll
    for (int st = 128; st; st >>= 1) {
        if (threadIdx.x < st) s[threadIdx.x] += s[threadIdx.x + st];
        __syncthreads();
    }
    if (threadIdx.x == 0) out[0] = s[0] / (float)NROWS;
}

// ---------------------------------------------------------------------------
extern "C" void kernel_launch(void* const* d_in, const int* in_sizes, int n_in,
                              void* d_out, int out_size) {
    const float* feat = (const float*)d_in[0];
    const int* pos = (const int*)d_in[1];
    const int* neg = (const int*)d_in[2];
    float* out = (float*)d_out;

    k_normalize<<<NROWS, 128>>>(feat);
    k_zero<<<NROWS / 256, 256>>>();
    dim3 grid(NROWS / BM, COL_SPLITS);
    k_main<<<grid, 256>>>(pos, neg);
    k_finalize<<<1, 256>>>(out);
}

// round 6
// speedup vs baseline: 7.2064x; 7.2064x over previous
#include <cuda_runtime.h>
#include <cuda_fp16.h>
#include <math.h>
#include <stdint.h>

// ===========================================================================
// MySupConLoss fused, round 5: fp16 mma.sync (HMMA.16816) GEMM + fused epilogue.
// tcgen05 is unavailable: harness lowers via compute_103 PTX (no 'a' target),
// so only sm_80-era PTX features exist. mma.sync/ldmatrix/cp.async all work.
//
// loss_i = log(sum_j e_ij*neg_ij) - (sum_j e_ij*pos_ij)/card_i
// e_ij = exp(sim_ij/T - m_i), m_i = ||fn_i||^2/T (diagonal dominates row max)
// out = mean_i loss_i
// ===========================================================================

#define NROWS 8192
#define DDIM  512
#define INV_T 14.285714285714286f

#define BM 128
#define BN 128
#define BK 32
#define NKT (DDIM / BK)        // 16 k-iterations
#define PITCH_H 40             // halves per smem row (32 + 8 pad)
#define PITCH_B 80             // bytes per smem row
#define TILE_BYTES (128 * PITCH_B)      // 10240 per operand tile
#define STAGE_BYTES (2 * TILE_BYTES)    // A + B
#define THREADS 256

// ---------------------------------------------------------------------------
// scratch
// ---------------------------------------------------------------------------
__device__ __half g_fn16[(size_t)NROWS * DDIM];  // normalized features, 8 MB
__device__ float  g_m[NROWS];
__device__ float  g_spos[NROWS];
__device__ float  g_sneg[NROWS];
__device__ float  g_card[NROWS];

// ---------------------------------------------------------------------------
// helpers
// ---------------------------------------------------------------------------
__device__ __forceinline__ uint32_t smem_u32(const void* p) {
    uint32_t a;
    asm("{ .reg .u64 t; cvta.to.shared.u64 t, %1; cvt.u32.u64 %0, t; }"
        : "=r"(a) : "l"(p));
    return a;
}
__device__ __forceinline__ void cp16(uint32_t s, const void* g) {
    asm volatile("cp.async.cg.shared.global [%0], [%1], 16;"
                 :: "r"(s), "l"(g) : "memory");
}
__device__ __forceinline__ void cp_commit() {
    asm volatile("cp.async.commit_group;" ::: "memory");
}
__device__ __forceinline__ void cp_wait0() {
    asm volatile("cp.async.wait_group 0;" ::: "memory");
}
__device__ __forceinline__ void ldm_x4(uint32_t a, uint32_t& r0, uint32_t& r1,
                                       uint32_t& r2, uint32_t& r3) {
    asm volatile("ldmatrix.sync.aligned.m8n8.x4.shared.b16 {%0,%1,%2,%3}, [%4];"
                 : "=r"(r0), "=r"(r1), "=r"(r2), "=r"(r3) : "r"(a));
}
__device__ __forceinline__ void mma16816(float* c, const uint32_t* a,
                                         uint32_t b0, uint32_t b1) {
    asm volatile(
        "mma.sync.aligned.m16n8k16.row.col.f32.f16.f16.f32 "
        "{%0,%1,%2,%3}, {%4,%5,%6,%7}, {%8,%9}, {%0,%1,%2,%3};"
        : "+f"(c[0]), "+f"(c[1]), "+f"(c[2]), "+f"(c[3])
        : "r"(a[0]), "r"(a[1]), "r"(a[2]), "r"(a[3]), "r"(b0), "r"(b1));
}

// ---------------------------------------------------------------------------
// Kernel 1: normalize rows -> fp16, compute m_i
// ---------------------------------------------------------------------------
__global__ __launch_bounds__(128) void k_normalize(const float* __restrict__ f) {
    int row = blockIdx.x;
    const float4* fr = reinterpret_cast<const float4*>(f + (size_t)row * DDIM);
    float4 v = fr[threadIdx.x];
    float ss = v.x * v.x + v.y * v.y + v.z * v.z + v.w * v.w;
    #pragma unroll
    for (int o = 16; o; o >>= 1) ss += __shfl_xor_sync(0xffffffffu, ss, o);
    __shared__ float s[4];
    if ((threadIdx.x & 31) == 0) s[threadIdx.x >> 5] = ss;
    __syncthreads();
    float tot = s[0] + s[1] + s[2] + s[3];
    float inv = 1.0f / fmaxf(sqrtf(tot), 1e-8f);
    __half2 h0 = __floats2half2_rn(v.x * inv, v.y * inv);
    __half2 h1 = __floats2half2_rn(v.z * inv, v.w * inv);
    __half2* out = reinterpret_cast<__half2*>(g_fn16 + (size_t)row * DDIM);
    out[threadIdx.x * 2 + 0] = h0;
    out[threadIdx.x * 2 + 1] = h1;
    if (threadIdx.x == 0) g_m[row] = tot * inv * inv * INV_T;
}

// ---------------------------------------------------------------------------
// Kernel 2: zero accumulators (every graph replay)
// ---------------------------------------------------------------------------
__global__ void k_zero() {
    int i = blockIdx.x * blockDim.x + threadIdx.x;
    if (i < NROWS) { g_spos[i] = 0.f; g_sneg[i] = 0.f; g_card[i] = 0.f; }
}

// ---------------------------------------------------------------------------
// Kernel 3: fused GEMM (mma.sync fp16) + exp/mask epilogue.
// 128x128 tile, 8 warps as 4(M) x 2(N), warp tile 32x64, BK=32, 2-stage cp.async.
// ---------------------------------------------------------------------------
__global__ __launch_bounds__(THREADS, 2) void k_main(const int* __restrict__ pos,
                                                     const int* __restrict__ neg) {
    __shared__ __align__(16) char smem_raw[2 * STAGE_BYTES];  // 40960 B
    const uint32_t sbase = smem_u32(smem_raw);

    const int tid = threadIdx.x;
    const int wid = tid >> 5;
    const int lane = tid & 31;
    const int warpM = wid & 3;       // 4 warps along M
    const int warpN = wid >> 2;      // 2 warps along N
    const int rowBase = blockIdx.x * BM;
    const int colBase = blockIdx.y * BN;

    // cp.async mapping: thread -> (row lr, 16B chunk), 2 rows per thread per tile
    const int lr = tid >> 2;               // 0..63
    const int ck = tid & 3;                // 16B chunk within BK (4 chunks)
    const __half* gA = g_fn16 + (size_t)(rowBase + lr) * DDIM + ck * 8;
    const __half* gB = g_fn16 + (size_t)(colBase + lr) * DDIM + ck * 8;
    const uint32_t sOffA = (uint32_t)(lr * PITCH_B + ck * 16);
    const uint32_t sOffB = (uint32_t)(TILE_BYTES + lr * PITCH_B + ck * 16);

    float acc[2][8][4];
    #pragma unroll
    for (int mt = 0; mt < 2; mt++)
        #pragma unroll
        for (int nt = 0; nt < 8; nt++)
            #pragma unroll
            for (int e = 0; e < 4; e++) acc[mt][nt][e] = 0.f;

    // ldmatrix bases (per stage add s*STAGE_BYTES)
    const uint32_t aBase = sbase + (uint32_t)((warpM * 32 + (lane & 15)) * PITCH_B +
                                              (lane >> 4) * 16);
    const uint32_t bBase = sbase + TILE_BYTES +
                           (uint32_t)((warpN * 64 + (lane & 15)) * PITCH_B +
                                      (lane >> 4) * 16);

    // prologue: stage 0 <- kt 0
    {
        const uint32_t st = sbase;
        cp16(st + sOffA, gA);
        cp16(st + sOffA + 64 * PITCH_B, gA + (size_t)64 * DDIM);
        cp16(st + sOffB, gB);
        cp16(st + sOffB + 64 * PITCH_B, gB + (size_t)64 * DDIM);
        cp_commit();
    }

    for (int kt = 0; kt < NKT; kt++) {
        cp_wait0();
        __syncthreads();
        if (kt + 1 < NKT) {
            const uint32_t st = sbase + ((kt + 1) & 1) * STAGE_BYTES;
            const size_t go = (size_t)(kt + 1) * BK;
            cp16(st + sOffA, gA + go);
            cp16(st + sOffA + 64 * PITCH_B, gA + go + (size_t)64 * DDIM);
            cp16(st + sOffB, gB + go);
            cp16(st + sOffB + 64 * PITCH_B, gB + go + (size_t)64 * DDIM);
            cp_commit();
        }
        const uint32_t stOff = (kt & 1) * STAGE_BYTES;
        #pragma unroll
        for (int ks = 0; ks < 2; ks++) {
            uint32_t areg[2][4];
            #pragma unroll
            for (int mt = 0; mt < 2; mt++)
                ldm_x4(aBase + stOff + mt * 16 * PITCH_B + ks * 32,
                       areg[mt][0], areg[mt][1], areg[mt][2], areg[mt][3]);
            uint32_t breg[4][4];
            #pragma unroll
            for (int p = 0; p < 4; p++)
                ldm_x4(bBase + stOff + p * 16 * PITCH_B + ks * 32,
                       breg[p][0], breg[p][1], breg[p][2], breg[p][3]);
            #pragma unroll
            for (int mt = 0; mt < 2; mt++)
                #pragma unroll
                for (int nt = 0; nt < 8; nt++) {
                    const int p = nt >> 1, hi = nt & 1;
                    mma16816(acc[mt][nt], areg[mt],
                             breg[p][hi ? 1 : 0], breg[p][hi ? 3 : 2]);
                }
        }
        __syncthreads();  // done reading this stage before it's refilled
    }

    // ---------------- fused epilogue ----------------
    #pragma unroll
    for (int mt = 0; mt < 2; mt++) {
        const int r0 = rowBase + warpM * 32 + mt * 16 + (lane >> 2);
        const int r1 = r0 + 8;
        const float mA = g_m[r0];
        const float mB = g_m[r1];
        const size_t o0 = (size_t)r0 * NROWS;
        const size_t o1 = (size_t)r1 * NROWS;
        float sp0 = 0.f, sn0 = 0.f, cd0 = 0.f;
        float sp1 = 0.f, sn1 = 0.f, cd1 = 0.f;
        #pragma unroll
        for (int nt = 0; nt < 8; nt++) {
            const int j = colBase + warpN * 64 + nt * 8 + (lane & 3) * 2;
            const float e00 = __expf(fmaf(acc[mt][nt][0], INV_T, -mA));
            const float e01 = __expf(fmaf(acc[mt][nt][1], INV_T, -mA));
            const float e10 = __expf(fmaf(acc[mt][nt][2], INV_T, -mB));
            const float e11 = __expf(fmaf(acc[mt][nt][3], INV_T, -mB));
            const int2 p0 = *reinterpret_cast<const int2*>(pos + o0 + j);
            const int2 n0 = *reinterpret_cast<const int2*>(neg + o0 + j);
            const int2 p1 = *reinterpret_cast<const int2*>(pos + o1 + j);
            const int2 n1 = *reinterpret_cast<const int2*>(neg + o1 + j);
            const bool v00 = (j != r0), v01 = (j + 1 != r0);
            const bool v10 = (j != r1), v11 = (j + 1 != r1);
            if (p0.x && v00) { sp0 += e00; cd0 += 1.f; }
            if (p0.y && v01) { sp0 += e01; cd0 += 1.f; }
            if (n0.x && v00) sn0 += e00;
            if (n0.y && v01) sn0 += e01;
            if (p1.x && v10) { sp1 += e10; cd1 += 1.f; }
            if (p1.y && v11) { sp1 += e11; cd1 += 1.f; }
            if (n1.x && v10) sn1 += e10;
            if (n1.y && v11) sn1 += e11;
        }
        #pragma unroll
        for (int o = 1; o <= 2; o <<= 1) {
            sp0 += __shfl_xor_sync(0xffffffffu, sp0, o);
            sn0 += __shfl_xor_sync(0xffffffffu, sn0, o);
            cd0 += __shfl_xor_sync(0xffffffffu, cd0, o);
            sp1 += __shfl_xor_sync(0xffffffffu, sp1, o);
            sn1 += __shfl_xor_sync(0xffffffffu, sn1, o);
            cd1 += __shfl_xor_sync(0xffffffffu, cd1, o);
        }
        if ((lane & 3) == 0) {
            atomicAdd(&g_spos[r0], sp0);
            atomicAdd(&g_sneg[r0], sn0);
            atomicAdd(&g_card[r0], cd0);
            atomicAdd(&g_spos[r1], sp1);
            atomicAdd(&g_sneg[r1], sn1);
            atomicAdd(&g_card[r1], cd1);
        }
    }
}

// ---------------------------------------------------------------------------
// Kernel 4: finalize
// ---------------------------------------------------------------------------
__global__ __launch_bounds__(256) void k_finalize(float* __restrict__ out) {
    __shared__ float s[256];
    float sum = 0.f;
    for (int i = threadIdx.x; i < NROWS; i += 256) {
        float c = g_card[i];
        float l = 0.f;
        if (c > 0.f) l = logf(g_sneg[i]) - g_spos[i] / c;
        sum += l;
    }
    s[threadIdx.x] = sum;
    __syncthreads();
    #pragma unroll
    for (int st = 128; st; st >>= 1) {
        if (threadIdx.x < st) s[threadIdx.x] += s[threadIdx.x + st];
        __syncthreads();
    }
    if (threadIdx.x == 0) out[0] = s[0] / (float)NROWS;
}

// ---------------------------------------------------------------------------
extern "C" void kernel_launch(void* const* d_in, const int* in_sizes, int n_in,
                              void* d_out, int out_size) {
    const float* feat = (const float*)d_in[0];
    const int* pos = (const int*)d_in[1];
    const int* neg = (const int*)d_in[2];
    float* out = (float*)d_out;

    k_normalize<<<NROWS, 128>>>(feat);
    k_zero<<<NROWS / 256, 256>>>();
    dim3 grid(NROWS / BM, NROWS / BN);
    k_main<<<grid, THREADS>>>(pos, neg);
    k_finalize<<<1, 256>>>(out);
}

// round 9
// speedup vs baseline: 10.0887x; 1.4000x over previous
#include <cuda_runtime.h>
#include <cuda_fp16.h>
#include <math.h>
#include <stdint.h>

// ===========================================================================
// MySupConLoss fused, round 6: symmetric-GEMM mma.sync fp16 + dual epilogue.
//   sim = fn·fn^T is symmetric -> compute only upper-triangular 128x128 blocks
//   (2080 instead of 4096). Off-diagonal blocks run a row-oriented epilogue
//   (rows I, masks [i][j], max m_i) AND a column-oriented epilogue on the
//   transposed fragment (cols J, masks [j][i], max m_j). Halves HMMA work;
//   mask bytes + exp count unchanged.
// Also: parallel k_finalize (was 36.8us single-block -> ~2us).
// ===========================================================================

#define NROWS 8192
#define DDIM  512
#define INV_T 14.285714285714286f

#define BM 128
#define BN 128
#define BK 32
#define NKT (DDIM / BK)        // 16 k-iterations
#define PITCH_H 40             // halves per smem row (32 + 8 pad)
#define PITCH_B 80             // bytes per smem row
#define TILE_BYTES (128 * PITCH_B)      // 10240 per operand tile
#define STAGE_BYTES (2 * TILE_BYTES)
#define THREADS 256
#define NBLK (NROWS / BM)      // 64 stripes
#define NPAIR (NBLK * (NBLK + 1) / 2)   // 2080 upper-tri blocks

// ---------------------------------------------------------------------------
__device__ __half g_fn16[(size_t)NROWS * DDIM];
__device__ float  g_m[NROWS];
__device__ float  g_spos[NROWS];
__device__ float  g_sneg[NROWS];
__device__ float  g_card[NROWS];

// ---------------------------------------------------------------------------
__device__ __forceinline__ uint32_t smem_u32(const void* p) {
    uint32_t a;
    asm("{ .reg .u64 t; cvta.to.shared.u64 t, %1; cvt.u32.u64 %0, t; }"
        : "=r"(a) : "l"(p));
    return a;
}
__device__ __forceinline__ void cp16(uint32_t s, const void* g) {
    asm volatile("cp.async.cg.shared.global [%0], [%1], 16;"
                 :: "r"(s), "l"(g) : "memory");
}
__device__ __forceinline__ void cp_commit() {
    asm volatile("cp.async.commit_group;" ::: "memory");
}
__device__ __forceinline__ void cp_wait0() {
    asm volatile("cp.async.wait_group 0;" ::: "memory");
}
__device__ __forceinline__ void ldm_x4(uint32_t a, uint32_t& r0, uint32_t& r1,
                                       uint32_t& r2, uint32_t& r3) {
    asm volatile("ldmatrix.sync.aligned.m8n8.x4.shared.b16 {%0,%1,%2,%3}, [%4];"
                 : "=r"(r0), "=r"(r1), "=r"(r2), "=r"(r3) : "r"(a));
}
__device__ __forceinline__ void mma16816(float* c, const uint32_t* a,
                                         uint32_t b0, uint32_t b1) {
    asm volatile(
        "mma.sync.aligned.m16n8k16.row.col.f32.f16.f16.f32 "
        "{%0,%1,%2,%3}, {%4,%5,%6,%7}, {%8,%9}, {%0,%1,%2,%3};"
        : "+f"(c[0]), "+f"(c[1]), "+f"(c[2]), "+f"(c[3])
        : "r"(a[0]), "r"(a[1]), "r"(a[2]), "r"(a[3]), "r"(b0), "r"(b1));
}

// ---------------------------------------------------------------------------
// Kernel 1: normalize rows -> fp16, compute m_i
// ---------------------------------------------------------------------------
__global__ __launch_bounds__(128) void k_normalize(const float* __restrict__ f) {
    int row = blockIdx.x;
    const float4* fr = reinterpret_cast<const float4*>(f + (size_t)row * DDIM);
    float4 v = fr[threadIdx.x];
    float ss = v.x * v.x + v.y * v.y + v.z * v.z + v.w * v.w;
    #pragma unroll
    for (int o = 16; o; o >>= 1) ss += __shfl_xor_sync(0xffffffffu, ss, o);
    __shared__ float s[4];
    if ((threadIdx.x & 31) == 0) s[threadIdx.x >> 5] = ss;
    __syncthreads();
    float tot = s[0] + s[1] + s[2] + s[3];
    float inv = 1.0f / fmaxf(sqrtf(tot), 1e-8f);
    __half2 h0 = __floats2half2_rn(v.x * inv, v.y * inv);
    __half2 h1 = __floats2half2_rn(v.z * inv, v.w * inv);
    __half2* out = reinterpret_cast<__half2*>(g_fn16 + (size_t)row * DDIM);
    out[threadIdx.x * 2 + 0] = h0;
    out[threadIdx.x * 2 + 1] = h1;
    if (threadIdx.x == 0) g_m[row] = tot * inv * inv * INV_T;
}

// ---------------------------------------------------------------------------
// Kernel 2: zero accumulators + output (every graph replay)
// ---------------------------------------------------------------------------
__global__ void k_zero(float* __restrict__ out) {
    int i = blockIdx.x * blockDim.x + threadIdx.x;
    if (i < NROWS) { g_spos[i] = 0.f; g_sneg[i] = 0.f; g_card[i] = 0.f; }
    if (i == 0) out[0] = 0.f;
}

// ---------------------------------------------------------------------------
// Kernel 3: fused symmetric GEMM + dual epilogue.
// ---------------------------------------------------------------------------
__global__ __launch_bounds__(THREADS, 2) void k_main(const int* __restrict__ pos,
                                                     const int* __restrict__ neg) {
    __shared__ __align__(16) char smem_raw[2 * STAGE_BYTES];
    const uint32_t sbase = smem_u32(smem_raw);

    // map linear block id -> upper-triangular pair (bi <= bj)
    int idx = blockIdx.x, bi = 0, len = NBLK;
    while (idx >= len) { idx -= len; bi++; len--; }
    const int bj = bi + idx;
    const bool offdiag = (bi != bj);

    const int tid = threadIdx.x;
    const int wid = tid >> 5;
    const int lane = tid & 31;
    const int warpM = wid & 3;
    const int warpN = wid >> 2;
    const int rowBase = bi * BM;
    const int colBase = bj * BN;

    const int lr = tid >> 2;
    const int ck = tid & 3;
    const __half* gA = g_fn16 + (size_t)(rowBase + lr) * DDIM + ck * 8;
    const __half* gB = g_fn16 + (size_t)(colBase + lr) * DDIM + ck * 8;
    const uint32_t sOffA = (uint32_t)(lr * PITCH_B + ck * 16);
    const uint32_t sOffB = (uint32_t)(TILE_BYTES + lr * PITCH_B + ck * 16);

    float acc[2][8][4];
    #pragma unroll
    for (int mt = 0; mt < 2; mt++)
        #pragma unroll
        for (int nt = 0; nt < 8; nt++)
            #pragma unroll
            for (int e = 0; e < 4; e++) acc[mt][nt][e] = 0.f;

    const uint32_t aBase = sbase + (uint32_t)((warpM * 32 + (lane & 15)) * PITCH_B +
                                              (lane >> 4) * 16);
    const uint32_t bBase = sbase + TILE_BYTES +
                           (uint32_t)((warpN * 64 + (lane & 15)) * PITCH_B +
                                      (lane >> 4) * 16);

    {   // prologue: stage 0 <- kt 0
        cp16(sbase + sOffA, gA);
        cp16(sbase + sOffA + 64 * PITCH_B, gA + (size_t)64 * DDIM);
        cp16(sbase + sOffB, gB);
        cp16(sbase + sOffB + 64 * PITCH_B, gB + (size_t)64 * DDIM);
        cp_commit();
    }

    for (int kt = 0; kt < NKT; kt++) {
        cp_wait0();
        __syncthreads();
        if (kt + 1 < NKT) {
            const uint32_t st = sbase + ((kt + 1) & 1) * STAGE_BYTES;
            const size_t go = (size_t)(kt + 1) * BK;
            cp16(st + sOffA, gA + go);
            cp16(st + sOffA + 64 * PITCH_B, gA + go + (size_t)64 * DDIM);
            cp16(st + sOffB, gB + go);
            cp16(st + sOffB + 64 * PITCH_B, gB + go + (size_t)64 * DDIM);
            cp_commit();
        }
        const uint32_t stOff = (kt & 1) * STAGE_BYTES;
        #pragma unroll
        for (int ks = 0; ks < 2; ks++) {
            uint32_t areg[2][4];
            #pragma unroll
            for (int mt = 0; mt < 2; mt++)
                ldm_x4(aBase + stOff + mt * 16 * PITCH_B + ks * 32,
                       areg[mt][0], areg[mt][1], areg[mt][2], areg[mt][3]);
            uint32_t breg[4][4];
            #pragma unroll
            for (int p = 0; p < 4; p++)
                ldm_x4(bBase + stOff + p * 16 * PITCH_B + ks * 32,
                       breg[p][0], breg[p][1], breg[p][2], breg[p][3]);
            #pragma unroll
            for (int mt = 0; mt < 2; mt++)
                #pragma unroll
                for (int nt = 0; nt < 8; nt++) {
                    const int p = nt >> 1, hi = nt & 1;
                    mma16816(acc[mt][nt], areg[mt],
                             breg[p][hi ? 1 : 0], breg[p][hi ? 3 : 2]);
                }
        }
        __syncthreads();
    }

    // ------------- epilogue 1: row-oriented (rows I, masks [i][j]) -------------
    #pragma unroll
    for (int mt = 0; mt < 2; mt++) {
        const int r0 = rowBase + warpM * 32 + mt * 16 + (lane >> 2);
        const int r1 = r0 + 8;
        const float mA = g_m[r0];
        const float mB = g_m[r1];
        const size_t o0 = (size_t)r0 * NROWS;
        const size_t o1 = (size_t)r1 * NROWS;
        float sp0 = 0.f, sn0 = 0.f, cd0 = 0.f;
        float sp1 = 0.f, sn1 = 0.f, cd1 = 0.f;
        #pragma unroll
        for (int nt = 0; nt < 8; nt++) {
            const int j = colBase + warpN * 64 + nt * 8 + (lane & 3) * 2;
            const float e00 = __expf(fmaf(acc[mt][nt][0], INV_T, -mA));
            const float e01 = __expf(fmaf(acc[mt][nt][1], INV_T, -mA));
            const float e10 = __expf(fmaf(acc[mt][nt][2], INV_T, -mB));
            const float e11 = __expf(fmaf(acc[mt][nt][3], INV_T, -mB));
            const int2 p0 = *reinterpret_cast<const int2*>(pos + o0 + j);
            const int2 n0 = *reinterpret_cast<const int2*>(neg + o0 + j);
            const int2 p1 = *reinterpret_cast<const int2*>(pos + o1 + j);
            const int2 n1 = *reinterpret_cast<const int2*>(neg + o1 + j);
            const bool v00 = (j != r0), v01 = (j + 1 != r0);
            const bool v10 = (j != r1), v11 = (j + 1 != r1);
            if (p0.x && v00) { sp0 += e00; cd0 += 1.f; }
            if (p0.y && v01) { sp0 += e01; cd0 += 1.f; }
            if (n0.x && v00) sn0 += e00;
            if (n0.y && v01) sn0 += e01;
            if (p1.x && v10) { sp1 += e10; cd1 += 1.f; }
            if (p1.y && v11) { sp1 += e11; cd1 += 1.f; }
            if (n1.x && v10) sn1 += e10;
            if (n1.y && v11) sn1 += e11;
        }
        #pragma unroll
        for (int o = 1; o <= 2; o <<= 1) {
            sp0 += __shfl_xor_sync(0xffffffffu, sp0, o);
            sn0 += __shfl_xor_sync(0xffffffffu, sn0, o);
            cd0 += __shfl_xor_sync(0xffffffffu, cd0, o);
            sp1 += __shfl_xor_sync(0xffffffffu, sp1, o);
            sn1 += __shfl_xor_sync(0xffffffffu, sn1, o);
            cd1 += __shfl_xor_sync(0xffffffffu, cd1, o);
        }
        if ((lane & 3) == 0) {
            atomicAdd(&g_spos[r0], sp0);
            atomicAdd(&g_sneg[r0], sn0);
            atomicAdd(&g_card[r0], cd0);
            atomicAdd(&g_spos[r1], sp1);
            atomicAdd(&g_sneg[r1], sn1);
            atomicAdd(&g_card[r1], cd1);
        }
    }

    // ------ epilogue 2 (off-diag): column-oriented (cols J, masks [j][i]) ------
    if (offdiag) {
        #pragma unroll
        for (int nt = 0; nt < 8; nt++) {
            const int j0 = colBase + warpN * 64 + nt * 8 + (lane & 3) * 2;
            const int j1 = j0 + 1;
            const float mJ0 = g_m[j0];
            const float mJ1 = g_m[j1];
            const size_t oj0 = (size_t)j0 * NROWS;
            const size_t oj1 = (size_t)j1 * NROWS;
            float spc0 = 0.f, snc0 = 0.f, cdc0 = 0.f;
            float spc1 = 0.f, snc1 = 0.f, cdc1 = 0.f;
            #pragma unroll
            for (int mt = 0; mt < 2; mt++) {
                const int r0 = rowBase + warpM * 32 + mt * 16 + (lane >> 2);
                const int r1 = r0 + 8;
                // e' with the COLUMN's max m_j
                const float e00 = __expf(fmaf(acc[mt][nt][0], INV_T, -mJ0)); // (r0,j0)
                const float e01 = __expf(fmaf(acc[mt][nt][1], INV_T, -mJ1)); // (r0,j1)
                const float e10 = __expf(fmaf(acc[mt][nt][2], INV_T, -mJ0)); // (r1,j0)
                const float e11 = __expf(fmaf(acc[mt][nt][3], INV_T, -mJ1)); // (r1,j1)
                const int pj00 = pos[oj0 + r0], pj01 = pos[oj1 + r0];
                const int pj10 = pos[oj0 + r1], pj11 = pos[oj1 + r1];
                const int nj00 = neg[oj0 + r0], nj01 = neg[oj1 + r0];
                const int nj10 = neg[oj0 + r1], nj11 = neg[oj1 + r1];
                if (pj00) { spc0 += e00; cdc0 += 1.f; }
                if (pj10) { spc0 += e10; cdc0 += 1.f; }
                if (nj00) snc0 += e00;
                if (nj10) snc0 += e10;
                if (pj01) { spc1 += e01; cdc1 += 1.f; }
                if (pj11) { spc1 += e11; cdc1 += 1.f; }
                if (nj01) snc1 += e01;
                if (nj11) snc1 += e11;
            }
            // reduce over rows (lanes differing in bits 2..4)
            #pragma unroll
            for (int o = 4; o <= 16; o <<= 1) {
                spc0 += __shfl_xor_sync(0xffffffffu, spc0, o);
                snc0 += __shfl_xor_sync(0xffffffffu, snc0, o);
                cdc0 += __shfl_xor_sync(0xffffffffu, cdc0, o);
                spc1 += __shfl_xor_sync(0xffffffffu, spc1, o);
                snc1 += __shfl_xor_sync(0xffffffffu, snc1, o);
                cdc1 += __shfl_xor_sync(0xffffffffu, cdc1, o);
            }
            if (lane < 4) {
                atomicAdd(&g_spos[j0], spc0);
                atomicAdd(&g_sneg[j0], snc0);
                atomicAdd(&g_card[j0], cdc0);
                atomicAdd(&g_spos[j1], spc1);
                atomicAdd(&g_sneg[j1], snc1);
                atomicAdd(&g_card[j1], cdc1);
            }
        }
    }
}

// ---------------------------------------------------------------------------
// Kernel 4: finalize (parallel: 32 blocks, atomicAdd of scaled partials)
// ---------------------------------------------------------------------------
__global__ __launch_bounds__(256) void k_finalize(float* __restrict__ out) {
    __shared__ float s[256];
    const int i = blockIdx.x * 256 + threadIdx.x;
    float c = g_card[i];
    float l = 0.f;
    if (c > 0.f) l = logf(g_sneg[i]) - g_spos[i] / c;
    s[threadIdx.x] = l;
    __syncthreads();
    #pragma unroll
    for (int st = 128; st; st >>= 1) {
        if (threadIdx.x < st) s[threadIdx.x] += s[threadIdx.x + st];
        __syncthreads();
    }
    if (threadIdx.x == 0) atomicAdd(out, s[0] * (1.0f / (float)NROWS));
}

// ---------------------------------------------------------------------------
extern "C" void kernel_launch(void* const* d_in, const int* in_sizes, int n_in,
                              void* d_out, int out_size) {
    const float* feat = (const float*)d_in[0];
    const int* pos = (const int*)d_in[1];
    const int* neg = (const int*)d_in[2];
    float* out = (float*)d_out;

    k_normalize<<<NROWS, 128>>>(feat);
    k_zero<<<NROWS / 256, 256>>>(out);
    k_main<<<NPAIR, THREADS>>>(pos, neg);
    k_finalize<<<NROWS / 256, 256>>>(out);
}

// round 10
// speedup vs baseline: 10.7619x; 1.0667x over previous
#include <cuda_runtime.h>
#include <cuda_fp16.h>
#include <math.h>
#include <stdint.h>

// ===========================================================================
// MySupConLoss fused, round 9: symmetric mma.sync GEMM + dual epilogue,
//   + L2 mask prefetch during the k-loop (overlap mask DRAM with HMMA)
//   + 3-stage cp.async pipeline, single __syncthreads per k-iter
//   + single-exp factorization: e_ij = exp2f(acc*C) * Einv[row or col]
//   + k_zero merged into k_normalize
// ===========================================================================

#define NROWS 8192
#define DDIM  512
#define INV_T 14.285714285714286f
#define EXP_C2 20.60992915555662f   // INV_T * log2(e)

#define BM 128
#define BN 128
#define BK 32
#define NKT (DDIM / BK)        // 16
#define PITCH_B 80             // bytes per smem row (32 halves + 8 pad)
#define TILE_BYTES (128 * PITCH_B)      // 10240
#define STAGE_BYTES (2 * TILE_BYTES)    // 20480 (A + B)
#define NST 3
#define SMEM_MAIN (NST * STAGE_BYTES)   // 61440 -> dynamic smem
#define THREADS 256
#define NBLK (NROWS / BM)
#define NPAIR (NBLK * (NBLK + 1) / 2)   // 2080

// ---------------------------------------------------------------------------
__device__ __half g_fn16[(size_t)NROWS * DDIM];
__device__ float  g_einv[NROWS];   // exp(-m_i)
__device__ float  g_spos[NROWS];
__device__ float  g_sneg[NROWS];
__device__ float  g_card[NROWS];

// ---------------------------------------------------------------------------
__device__ __forceinline__ uint32_t smem_u32(const void* p) {
    uint32_t a;
    asm("{ .reg .u64 t; cvta.to.shared.u64 t, %1; cvt.u32.u64 %0, t; }"
        : "=r"(a) : "l"(p));
    return a;
}
__device__ __forceinline__ void cp16(uint32_t s, const void* g) {
    asm volatile("cp.async.cg.shared.global [%0], [%1], 16;"
                 :: "r"(s), "l"(g) : "memory");
}
__device__ __forceinline__ void cp_commit() {
    asm volatile("cp.async.commit_group;" ::: "memory");
}
__device__ __forceinline__ void cp_wait1() {
    asm volatile("cp.async.wait_group 1;" ::: "memory");
}
__device__ __forceinline__ void l2_prefetch(const void* g) {
    asm volatile("prefetch.global.L2 [%0];" :: "l"(g));
}
__device__ __forceinline__ void ldm_x4(uint32_t a, uint32_t& r0, uint32_t& r1,
                                       uint32_t& r2, uint32_t& r3) {
    asm volatile("ldmatrix.sync.aligned.m8n8.x4.shared.b16 {%0,%1,%2,%3}, [%4];"
                 : "=r"(r0), "=r"(r1), "=r"(r2), "=r"(r3) : "r"(a));
}
__device__ __forceinline__ void mma16816(float* c, const uint32_t* a,
                                         uint32_t b0, uint32_t b1) {
    asm volatile(
        "mma.sync.aligned.m16n8k16.row.col.f32.f16.f16.f32 "
        "{%0,%1,%2,%3}, {%4,%5,%6,%7}, {%8,%9}, {%0,%1,%2,%3};"
        : "+f"(c[0]), "+f"(c[1]), "+f"(c[2]), "+f"(c[3])
        : "r"(a[0]), "r"(a[1]), "r"(a[2]), "r"(a[3]), "r"(b0), "r"(b1));
}

// ---------------------------------------------------------------------------
// Kernel 1: normalize -> fp16, einv = exp(-m_i), zero accumulators + out
// ---------------------------------------------------------------------------
__global__ __launch_bounds__(128) void k_normalize(const float* __restrict__ f,
                                                   float* __restrict__ out) {
    int row = blockIdx.x;
    const float4* fr = reinterpret_cast<const float4*>(f + (size_t)row * DDIM);
    float4 v = fr[threadIdx.x];
    float ss = v.x * v.x + v.y * v.y + v.z * v.z + v.w * v.w;
    #pragma unroll
    for (int o = 16; o; o >>= 1) ss += __shfl_xor_sync(0xffffffffu, ss, o);
    __shared__ float s[4];
    if ((threadIdx.x & 31) == 0) s[threadIdx.x >> 5] = ss;
    __syncthreads();
    float tot = s[0] + s[1] + s[2] + s[3];
    float inv = 1.0f / fmaxf(sqrtf(tot), 1e-8f);
    __half2 h0 = __floats2half2_rn(v.x * inv, v.y * inv);
    __half2 h1 = __floats2half2_rn(v.z * inv, v.w * inv);
    __half2* o2 = reinterpret_cast<__half2*>(g_fn16 + (size_t)row * DDIM);
    o2[threadIdx.x * 2 + 0] = h0;
    o2[threadIdx.x * 2 + 1] = h1;
    if (threadIdx.x == 0) {
        g_einv[row] = expf(-(tot * inv * inv * INV_T));
        g_spos[row] = 0.f; g_sneg[row] = 0.f; g_card[row] = 0.f;
        if (row == 0) out[0] = 0.f;
    }
}

// ---------------------------------------------------------------------------
// Kernel 2: fused symmetric GEMM + dual epilogue.
// ---------------------------------------------------------------------------
__global__ __launch_bounds__(THREADS, 2) void k_main(const int* __restrict__ pos,
                                                     const int* __restrict__ neg) {
    extern __shared__ __align__(16) char smem_raw[];
    const uint32_t sbase = smem_u32(smem_raw);

    // linear block id -> upper-triangular (bi <= bj)
    int idx = blockIdx.x, bi = 0, len = NBLK;
    while (idx >= len) { idx -= len; bi++; len--; }
    const int bj = bi + idx;
    const bool offdiag = (bi != bj);

    const int tid = threadIdx.x;
    const int wid = tid >> 5;
    const int lane = tid & 31;
    const int warpM = wid & 3;
    const int warpN = wid >> 2;
    const int rowBase = bi * BM;
    const int colBase = bj * BN;

    const int lr = tid >> 2;
    const int ck = tid & 3;
    const __half* gA = g_fn16 + (size_t)(rowBase + lr) * DDIM + ck * 8;
    const __half* gB = g_fn16 + (size_t)(colBase + lr) * DDIM + ck * 8;
    const uint32_t sOffA = (uint32_t)(lr * PITCH_B + ck * 16);
    const uint32_t sOffB = (uint32_t)(TILE_BYTES + lr * PITCH_B + ck * 16);

    float acc[2][8][4];
    #pragma unroll
    for (int mt = 0; mt < 2; mt++)
        #pragma unroll
        for (int nt = 0; nt < 8; nt++)
            #pragma unroll
            for (int e = 0; e < 4; e++) acc[mt][nt][e] = 0.f;

    const uint32_t aBase = sbase + (uint32_t)((warpM * 32 + (lane & 15)) * PITCH_B +
                                              (lane >> 4) * 16);
    const uint32_t bBase = sbase + TILE_BYTES +
                           (uint32_t)((warpN * 64 + (lane & 15)) * PITCH_B +
                                      (lane >> 4) * 16);

    // prologue: stages 0,1 <- kt 0,1 (two commit groups)
    #pragma unroll
    for (int kp = 0; kp < 2; kp++) {
        const uint32_t st = sbase + kp * STAGE_BYTES;
        const size_t go = (size_t)kp * BK;
        cp16(st + sOffA, gA + go);
        cp16(st + sOffA + 64 * PITCH_B, gA + go + (size_t)64 * DDIM);
        cp16(st + sOffB, gB + go);
        cp16(st + sOffB + 64 * PITCH_B, gB + go + (size_t)64 * DDIM);
        cp_commit();
    }

    for (int kt = 0; kt < NKT; kt++) {
        cp_wait1();          // stage kt%3 ready (one younger group may be pending)
        __syncthreads();     // also orders last iter's reads before stage reuse

        // L2 prefetch of this block's mask regions, spread over the k-loop.
        // Regions (64 KB each = 512 lines): 0 pos rows, 1 neg rows,
        // 2 pos cols (transposed), 3 neg cols. 4 kts per region, 128 lines/kt.
        if (tid < 128) {
            const int reg = kt >> 2;
            const int li = ((kt & 3) << 7) + tid;       // 0..511
            const int rr = li >> 2;
            const int off = (li & 3) << 5;              // ints
            const int* base = (reg & 1) ? neg : pos;
            const size_t adr = (reg < 2)
                ? (size_t)(rowBase + rr) * NROWS + colBase + off
                : (size_t)(colBase + rr) * NROWS + rowBase + off;
            l2_prefetch(base + adr);
        }

        if (kt + 2 < NKT) {
            const uint32_t st = sbase + ((kt + 2) % NST) * STAGE_BYTES;
            const size_t go = (size_t)(kt + 2) * BK;
            cp16(st + sOffA, gA + go);
            cp16(st + sOffA + 64 * PITCH_B, gA + go + (size_t)64 * DDIM);
            cp16(st + sOffB, gB + go);
            cp16(st + sOffB + 64 * PITCH_B, gB + go + (size_t)64 * DDIM);
        }
        cp_commit();         // uniform group accounting (empty at tail)

        const uint32_t stOff = (kt % NST) * STAGE_BYTES;
        #pragma unroll
        for (int ks = 0; ks < 2; ks++) {
            uint32_t areg[2][4];
            #pragma unroll
            for (int mt = 0; mt < 2; mt++)
                ldm_x4(aBase + stOff + mt * 16 * PITCH_B + ks * 32,
                       areg[mt][0], areg[mt][1], areg[mt][2], areg[mt][3]);
            uint32_t breg[4][4];
            #pragma unroll
            for (int p = 0; p < 4; p++)
                ldm_x4(bBase + stOff + p * 16 * PITCH_B + ks * 32,
                       breg[p][0], breg[p][1], breg[p][2], breg[p][3]);
            #pragma unroll
            for (int mt = 0; mt < 2; mt++)
                #pragma unroll
                for (int nt = 0; nt < 8; nt++) {
                    const int p = nt >> 1, hi = nt & 1;
                    mma16816(acc[mt][nt], areg[mt],
                             breg[p][hi ? 1 : 0], breg[p][hi ? 3 : 2]);
                }
        }
    }

    // ---- epilogue 1: row-oriented. x = exp2f(acc*C) overwrites acc; e = x*Ei.
    #pragma unroll
    for (int mt = 0; mt < 2; mt++) {
        const int r0 = rowBase + warpM * 32 + mt * 16 + (lane >> 2);
        const int r1 = r0 + 8;
        const float EiA = g_einv[r0];
        const float EiB = g_einv[r1];
        const size_t o0 = (size_t)r0 * NROWS;
        const size_t o1 = (size_t)r1 * NROWS;
        float sp0 = 0.f, sn0 = 0.f, cd0 = 0.f;
        float sp1 = 0.f, sn1 = 0.f, cd1 = 0.f;
        #pragma unroll
        for (int nt = 0; nt < 8; nt++) {
            const int j = colBase + warpN * 64 + nt * 8 + (lane & 3) * 2;
            const float x00 = exp2f(acc[mt][nt][0] * EXP_C2);
            const float x01 = exp2f(acc[mt][nt][1] * EXP_C2);
            const float x10 = exp2f(acc[mt][nt][2] * EXP_C2);
            const float x11 = exp2f(acc[mt][nt][3] * EXP_C2);
            acc[mt][nt][0] = x00; acc[mt][nt][1] = x01;
            acc[mt][nt][2] = x10; acc[mt][nt][3] = x11;
            const float e00 = x00 * EiA, e01 = x01 * EiA;
            const float e10 = x10 * EiB, e11 = x11 * EiB;
            const int2 p0 = *reinterpret_cast<const int2*>(pos + o0 + j);
            const int2 n0 = *reinterpret_cast<const int2*>(neg + o0 + j);
            const int2 p1 = *reinterpret_cast<const int2*>(pos + o1 + j);
            const int2 n1 = *reinterpret_cast<const int2*>(neg + o1 + j);
            const bool v00 = (j != r0), v01 = (j + 1 != r0);
            const bool v10 = (j != r1), v11 = (j + 1 != r1);
            if (p0.x && v00) { sp0 += e00; cd0 += 1.f; }
            if (p0.y && v01) { sp0 += e01; cd0 += 1.f; }
            if (n0.x && v00) sn0 += e00;
            if (n0.y && v01) sn0 += e01;
            if (p1.x && v10) { sp1 += e10; cd1 += 1.f; }
            if (p1.y && v11) { sp1 += e11; cd1 += 1.f; }
            if (n1.x && v10) sn1 += e10;
            if (n1.y && v11) sn1 += e11;
        }
        #pragma unroll
        for (int o = 1; o <= 2; o <<= 1) {
            sp0 += __shfl_xor_sync(0xffffffffu, sp0, o);
            sn0 += __shfl_xor_sync(0xffffffffu, sn0, o);
            cd0 += __shfl_xor_sync(0xffffffffu, cd0, o);
            sp1 += __shfl_xor_sync(0xffffffffu, sp1, o);
            sn1 += __shfl_xor_sync(0xffffffffu, sn1, o);
            cd1 += __shfl_xor_sync(0xffffffffu, cd1, o);
        }
        if ((lane & 3) == 0) {
            atomicAdd(&g_spos[r0], sp0);
            atomicAdd(&g_sneg[r0], sn0);
            atomicAdd(&g_card[r0], cd0);
            atomicAdd(&g_spos[r1], sp1);
            atomicAdd(&g_sneg[r1], sn1);
            atomicAdd(&g_card[r1], cd1);
        }
    }

    // ---- epilogue 2 (off-diag): column-oriented, e' = x * Ej (x reused).
    if (offdiag) {
        #pragma unroll
        for (int nt = 0; nt < 8; nt++) {
            const int j0 = colBase + warpN * 64 + nt * 8 + (lane & 3) * 2;
            const int j1 = j0 + 1;
            const float Ej0 = g_einv[j0];
            const float Ej1 = g_einv[j1];
            const size_t oj0 = (size_t)j0 * NROWS;
            const size_t oj1 = (size_t)j1 * NROWS;
            float spc0 = 0.f, snc0 = 0.f, cdc0 = 0.f;
            float spc1 = 0.f, snc1 = 0.f, cdc1 = 0.f;
            #pragma unroll
            for (int mt = 0; mt < 2; mt++) {
                const int r0 = rowBase + warpM * 32 + mt * 16 + (lane >> 2);
                const int r1 = r0 + 8;
                const float e00 = acc[mt][nt][0] * Ej0;  // (r0,j0)
                const float e01 = acc[mt][nt][1] * Ej1;  // (r0,j1)
                const float e10 = acc[mt][nt][2] * Ej0;  // (r1,j0)
                const float e11 = acc[mt][nt][3] * Ej1;  // (r1,j1)
                const int pj00 = pos[oj0 + r0], pj01 = pos[oj1 + r0];
                const int pj10 = pos[oj0 + r1], pj11 = pos[oj1 + r1];
                const int nj00 = neg[oj0 + r0], nj01 = neg[oj1 + r0];
                const int nj10 = neg[oj0 + r1], nj11 = neg[oj1 + r1];
                if (pj00) { spc0 += e00; cdc0 += 1.f; }
                if (pj10) { spc0 += e10; cdc0 += 1.f; }
                if (nj00) snc0 += e00;
                if (nj10) snc0 += e10;
                if (pj01) { spc1 += e01; cdc1 += 1.f; }
                if (pj11) { spc1 += e11; cdc1 += 1.f; }
                if (nj01) snc1 += e01;
                if (nj11) snc1 += e11;
            }
            #pragma unroll
            for (int o = 4; o <= 16; o <<= 1) {
                spc0 += __shfl_xor_sync(0xffffffffu, spc0, o);
                snc0 += __shfl_xor_sync(0xffffffffu, snc0, o);
                cdc0 += __shfl_xor_sync(0xffffffffu, cdc0, o);
                spc1 += __shfl_xor_sync(0xffffffffu, spc1, o);
                snc1 += __shfl_xor_sync(0xffffffffu, snc1, o);
                cdc1 += __shfl_xor_sync(0xffffffffu, cdc1, o);
            }
            if (lane < 4) {
                atomicAdd(&g_spos[j0], spc0);
                atomicAdd(&g_sneg[j0], snc0);
                atomicAdd(&g_card[j0], cdc0);
                atomicAdd(&g_spos[j1], spc1);
                atomicAdd(&g_sneg[j1], snc1);
                atomicAdd(&g_card[j1], cdc1);
            }
        }
    }
}

// ---------------------------------------------------------------------------
// Kernel 3: finalize (parallel, atomicAdd of scaled partials)
// ---------------------------------------------------------------------------
__global__ __launch_bounds__(256) void k_finalize(float* __restrict__ out) {
    __shared__ float s[256];
    const int i = blockIdx.x * 256 + threadIdx.x;
    float c = g_card[i];
    float l = 0.f;
    if (c > 0.f) l = logf(g_sneg[i]) - g_spos[i] / c;
    s[threadIdx.x] = l;
    __syncthreads();
    #pragma unroll
    for (int st = 128; st; st >>= 1) {
        if (threadIdx.x < st) s[threadIdx.x] += s[threadIdx.x + st];
        __syncthreads();
    }
    if (threadIdx.x == 0) atomicAdd(out, s[0] * (1.0f / (float)NROWS));
}

// ---------------------------------------------------------------------------
extern "C" void kernel_launch(void* const* d_in, const int* in_sizes, int n_in,
                              void* d_out, int out_size) {
    const float* feat = (const float*)d_in[0];
    const int* pos = (const int*)d_in[1];
    const int* neg = (const int*)d_in[2];
    float* out = (float*)d_out;

    cudaFuncSetAttribute(k_main, cudaFuncAttributeMaxDynamicSharedMemorySize,
                         SMEM_MAIN);

    k_normalize<<<NROWS, 128>>>(feat, out);
    k_main<<<NPAIR, THREADS, SMEM_MAIN>>>(pos, neg);
    k_finalize<<<NROWS / 256, 256>>>(out);
}